// round 13
// baseline (speedup 1.0000x reference)
// LogEntmaxBisect — log(entmax_1.5(X)) for X[4096, 32000] fp32.
//
// R13 = R12 scheme at NT=256 with 6 CTAs/SM (was 384/4): same 48 warps/SM
// but 50% more independent CTA phase streams -> flatter DRAM demand across
// the per-row reduce/solve bubbles; waves 6.9 -> 4.6. Staging shrinks to
// 32KB/CTA (6 x 32.8KB = 197KB smem). Otherwise identical: pass 1 stages
// head via __ldcs+STS and streams tail via 256-bit L2::evict_last loads;
// warp-0 funnel solve (fp64 accum, fp32 sqrt/log); pass 2 does the L2
// re-read loop FIRST (batched __ldcs) then drains the smem-staged head;
// all outputs via __stcs.

#include <cuda_runtime.h>
#include <math.h>

#define D_DIM   32000
#define NT      256
#define NVROW   (D_DIM / 4)       // 8000 float4 per row
#define NROW8   (D_DIM / 8)       // 4000 float8 per row
#define SH4     2048              // staged float4 count (32768 B)
#define SH8     (SH4 / 2)         // 1024 (float8 boundary)
#define NITER_A 8                 // 2048/256 exact        (staged head)
#define NITER_B 12                // ceil((4000-1024)/256) (256b tail)
#define NITER_C 24                // ceil((8000-2048)/256) (L2 re-read)
#define NWARP   (NT / 32)         // 8
#define TAU_GAP 0.005590169943749474   // (1/d)^(alpha-1) = 1/sqrt(32000)
#define TWO_LN2 1.3862943611198906f

// 256-bit load with L2 evict_last (keep for this CTA's pass-2 reuse)
__device__ __forceinline__ void ldg256_keep(const float* p, float* v)
{
    unsigned r0, r1, r2, r3, r4, r5, r6, r7;
    asm("ld.global.L2::evict_last.v8.b32 {%0,%1,%2,%3,%4,%5,%6,%7}, [%8];"
        : "=r"(r0), "=r"(r1), "=r"(r2), "=r"(r3),
          "=r"(r4), "=r"(r5), "=r"(r6), "=r"(r7) : "l"(p));
    v[0] = __uint_as_float(r0); v[1] = __uint_as_float(r1);
    v[2] = __uint_as_float(r2); v[3] = __uint_as_float(r3);
    v[4] = __uint_as_float(r4); v[5] = __uint_as_float(r5);
    v[6] = __uint_as_float(r6); v[7] = __uint_as_float(r7);
}

__global__ void __launch_bounds__(NT, 6)
log_entmax_kernel(const float* __restrict__ X, float* __restrict__ Y)
{
    const int tid  = threadIdx.x;
    const int lane = tid & 31;
    const int wid  = tid >> 5;          // 0..7

    __shared__ float4 stage[SH4];       // 32768 B row head
    __shared__ float  sred[4 * NWARP];
    __shared__ float  sbc[3];           // [0]=tau [1]=-log(Z) or sentinel [2]=tau_hi

    const size_t base = (size_t)blockIdx.x * D_DIM;
    const float*  __restrict__ Xs = X + base;
    const float4* __restrict__ Xr = (const float4*)Xs;
    float4*       __restrict__ Yr = (float4*)(Y + base);

    // ---- Pass 1a: staged head — __ldcs + STS, accumulate stats ---------
    float M = -3.0e38f, mn = 3.0e38f, S1 = 0.0f, S2 = 0.0f;
    #pragma unroll
    for (int j = 0; j < NITER_A; j++) {
        const int i4 = tid + j * NT;              // < SH4 always (exact)
        const float4 v = __ldcs(&Xr[i4]);         // to smem; no L2 reuse
        stage[i4] = v;
        M  = fmaxf(M,  fmaxf(fmaxf(v.x, v.y), fmaxf(v.z, v.w)));
        mn = fminf(mn, fminf(fminf(v.x, v.y), fminf(v.z, v.w)));
        S1 += ((v.x + v.y) + (v.z + v.w));
        S2 = fmaf(v.x, v.x, S2); S2 = fmaf(v.y, v.y, S2);
        S2 = fmaf(v.z, v.z, S2); S2 = fmaf(v.w, v.w, S2);
    }
    // ---- Pass 1b: tail — 256-bit evict_last loads ----------------------
    #pragma unroll
    for (int j = 0; j < NITER_B; j++) {
        const int i8 = SH8 + tid + j * NT;
        if (i8 < NROW8) {
            float v[8];
            ldg256_keep(Xs + i8 * 8, v);
            #pragma unroll
            for (int q = 0; q < 8; q++) {
                M  = fmaxf(M,  v[q]);
                mn = fminf(mn, v[q]);
                S1 += v[q];
                S2 = fmaf(v[q], v[q], S2);
            }
        }
    }

    // ---- Single block reduction of 4 values ----------------------------
    #pragma unroll
    for (int o = 16; o > 0; o >>= 1) {
        M  = fmaxf(M,  __shfl_xor_sync(0xffffffffu, M,  o));
        mn = fminf(mn, __shfl_xor_sync(0xffffffffu, mn, o));
        S1 += __shfl_xor_sync(0xffffffffu, S1, o);
        S2 += __shfl_xor_sync(0xffffffffu, S2, o);
    }
    if (lane == 0) {
        sred[wid] = M; sred[NWARP + wid] = mn;
        sred[2 * NWARP + wid] = S1; sred[3 * NWARP + wid] = S2;
    }
    __syncthreads();
    if (wid == 0) {
        float m = (lane < NWARP) ? sred[lane]             : -3.0e38f;
        float n = (lane < NWARP) ? sred[NWARP + lane]     :  3.0e38f;
        float a = (lane < NWARP) ? sred[2 * NWARP + lane] :  0.0f;
        float b = (lane < NWARP) ? sred[3 * NWARP + lane] :  0.0f;
        #pragma unroll
        for (int o = 4; o > 0; o >>= 1) {
            m = fmaxf(m, __shfl_xor_sync(0xffffffffu, m, o));
            n = fminf(n, __shfl_xor_sync(0xffffffffu, n, o));
            a += __shfl_xor_sync(0xffffffffu, a, o);
            b += __shfl_xor_sync(0xffffffffu, b, o);
        }
        if (lane == 0) {
            // Scalar solve: fp64 accumulation, fp32 sqrt/log
            const double d   = (double)D_DIM;
            const double mu  = 0.5 * (double)a / d;
            const double S2q = 0.25 * (double)b;
            const double V   = S2q - d * mu * mu;        // Sum (Xs - mu)^2
            const double m2  = 0.5 * (double)m;
            const double thi = m2 - TAU_GAP;             // tau_hi
            const double arg = (1.0 - V) / d;
            double t = (arg > 0.0) ? (mu - (double)sqrtf((float)arg)) : (m2 - 1.0);
            if (t > thi)      t = thi;
            if (t < m2 - 1.0) t = m2 - 1.0;
            const float tauf = (float)t;
            const bool dense = (arg > 0.0) && (0.5 * (double)n > (double)tauf);
            const double dmu = mu - (double)tauf;
            const double Z   = V + d * dmu * dmu;        // ~1 by construction
            sbc[0] = tauf;
            sbc[1] = dense ? (-__logf((float)Z)) : 1.0e30f;  // sentinel -> refine
            sbc[2] = (float)thi;
        }
    }
    __syncthreads();
    float tau = sbc[0];
    float nlZ = sbc[1];

    // ---- Fallback: one generic active-set quadratic refinement ---------
    // (plain re-read; never taken on dense-support data)
    if (nlZ > 1.0e29f) {                   // uniform across block
        __syncthreads();
        float C = 0.0f, F1 = 0.0f, F2 = 0.0f;
        #pragma unroll 4
        for (int j = 0; j < 32; j++) {     // ceil(8000/256)
            const int i4 = tid + j * NT;
            if (i4 < NVROW) {
                const float4 v = Xr[i4];
                #pragma unroll
                for (int q = 0; q < 4; q++) {
                    const float xv = (q == 0) ? v.x : (q == 1) ? v.y : (q == 2) ? v.z : v.w;
                    const float t = fmaf(xv, 0.5f, -tau);
                    const float rr = fmaxf(t, 0.0f);
                    if (t > 0.0f) C += 1.0f;
                    F1 += rr;
                    F2 = fmaf(rr, rr, F2);
                }
            }
        }
        #pragma unroll
        for (int o = 16; o > 0; o >>= 1) {
            C  += __shfl_xor_sync(0xffffffffu, C,  o);
            F1 += __shfl_xor_sync(0xffffffffu, F1, o);
            F2 += __shfl_xor_sync(0xffffffffu, F2, o);
        }
        if (lane == 0) { sred[wid] = C; sred[NWARP + wid] = F1; sred[2 * NWARP + wid] = F2; }
        __syncthreads();
        if (wid == 0) {
            float c  = (lane < NWARP) ? sred[lane]             : 0.0f;
            float f1 = (lane < NWARP) ? sred[NWARP + lane]     : 0.0f;
            float f2 = (lane < NWARP) ? sred[2 * NWARP + lane] : 0.0f;
            #pragma unroll
            for (int o = 4; o > 0; o >>= 1) {
                c  += __shfl_xor_sync(0xffffffffu, c,  o);
                f1 += __shfl_xor_sync(0xffffffffu, f1, o);
                f2 += __shfl_xor_sync(0xffffffffu, f2, o);
            }
            if (lane == 0) {
                float disc = fmaxf(fmaf(-c, f2 - 1.0f, f1 * f1), 0.0f);
                const float delta = (f1 - sqrtf(disc)) / c;
                const float tn = fminf(tau + delta, sbc[2]);
                const float dd = tn - tau;
                const float Zr = fmaf(c, dd * dd, fmaf(-2.0f * f1, dd, f2));
                sbc[0] = tn;
                sbc[1] = -__logf(fmaxf(Zr, 1.0e-30f));
            }
        }
        __syncthreads();
        tau = sbc[0];
        nlZ = sbc[1];
    }

    // ---- Pass 2a: tail re-read (L2-hot, last-use) FIRST ----------------
    #pragma unroll 4
    for (int j = 0; j < NITER_C; j++) {
        const int i4 = SH4 + tid + j * NT;
        if (i4 < NVROW) {
            const float4 v = __ldcs(&Xr[i4]);
            float4 o;
            o.x = fmaf(TWO_LN2, __log2f(fmaxf(fmaf(v.x, 0.5f, -tau), 0.0f)), nlZ);
            o.y = fmaf(TWO_LN2, __log2f(fmaxf(fmaf(v.y, 0.5f, -tau), 0.0f)), nlZ);
            o.z = fmaf(TWO_LN2, __log2f(fmaxf(fmaf(v.z, 0.5f, -tau), 0.0f)), nlZ);
            o.w = fmaf(TWO_LN2, __log2f(fmaxf(fmaf(v.w, 0.5f, -tau), 0.0f)), nlZ);
            __stcs(&Yr[i4], o);
        }
    }
    // ---- Pass 2b: staged head from smem, stream output -----------------
    #pragma unroll 4
    for (int j = 0; j < NITER_A; j++) {
        const int i4 = tid + j * NT;              // < SH4 always (exact)
        const float4 v = stage[i4];
        float4 o;
        o.x = fmaf(TWO_LN2, __log2f(fmaxf(fmaf(v.x, 0.5f, -tau), 0.0f)), nlZ);
        o.y = fmaf(TWO_LN2, __log2f(fmaxf(fmaf(v.y, 0.5f, -tau), 0.0f)), nlZ);
        o.z = fmaf(TWO_LN2, __log2f(fmaxf(fmaf(v.z, 0.5f, -tau), 0.0f)), nlZ);
        o.w = fmaf(TWO_LN2, __log2f(fmaxf(fmaf(v.w, 0.5f, -tau), 0.0f)), nlZ);
        __stcs(&Yr[i4], o);
    }
}

extern "C" void kernel_launch(void* const* d_in, const int* in_sizes, int n_in,
                              void* d_out, int out_size)
{
    const float* X = (const float*)d_in[0];
    float*       Y = (float*)d_out;
    const int rows = in_sizes[0] / D_DIM;     // 4096
    log_entmax_kernel<<<rows, NT>>>(X, Y);
}

// round 14
// speedup vs baseline: 1.1833x; 1.1833x over previous
// LogEntmaxBisect — log(entmax_1.5(X)) for X[4096, 32000] fp32.
//
// R14 = R12 (best, 166.7us; NT=384, 4 CTAs/SM, 48KB staging) with ONE
// change: pass-2a L2 re-read uses 256-bit ld.global.L2::evict_first.v8.b32
// (half the LDG count, double bytes/load in flight) instead of 128-bit
// __ldcs. R13 lesson confirmed: aggregate load-MLP is the binding resource;
// NT=256/6CTAs cut it and lost 44us.

#include <cuda_runtime.h>
#include <math.h>

#define D_DIM   32000
#define NT      384
#define NVROW   (D_DIM / 4)       // 8000 float4 per row
#define NROW8   (D_DIM / 8)       // 4000 float8 per row
#define SH4     3008              // staged float4 count (48128 B)
#define SH8     (SH4 / 2)         // 1504 (float8 boundary)
#define NITER_A 8                 // ceil(3008 / 384)      (staged head)
#define NITER_B 7                 // ceil((4000-1504)/384) (256b tail, pass 1)
#define NITER_C8 7                // ceil((4000-1504)/384) (256b re-read, pass 2)
#define NWARP   (NT / 32)         // 12
#define TAU_GAP 0.005590169943749474   // (1/d)^(alpha-1) = 1/sqrt(32000)
#define TWO_LN2 1.3862943611198906f

// 256-bit load, L2 evict_last (pass 1 tail: keep for pass-2 reuse)
__device__ __forceinline__ void ldg256_keep(const float* p, float* v)
{
    unsigned r0, r1, r2, r3, r4, r5, r6, r7;
    asm("ld.global.L2::evict_last.v8.b32 {%0,%1,%2,%3,%4,%5,%6,%7}, [%8];"
        : "=r"(r0), "=r"(r1), "=r"(r2), "=r"(r3),
          "=r"(r4), "=r"(r5), "=r"(r6), "=r"(r7) : "l"(p));
    v[0] = __uint_as_float(r0); v[1] = __uint_as_float(r1);
    v[2] = __uint_as_float(r2); v[3] = __uint_as_float(r3);
    v[4] = __uint_as_float(r4); v[5] = __uint_as_float(r5);
    v[6] = __uint_as_float(r6); v[7] = __uint_as_float(r7);
}

// 256-bit load, L2 evict_first (pass 2 re-read: last use)
__device__ __forceinline__ void ldg256_stream(const float* p, float* v)
{
    unsigned r0, r1, r2, r3, r4, r5, r6, r7;
    asm("ld.global.L2::evict_first.v8.b32 {%0,%1,%2,%3,%4,%5,%6,%7}, [%8];"
        : "=r"(r0), "=r"(r1), "=r"(r2), "=r"(r3),
          "=r"(r4), "=r"(r5), "=r"(r6), "=r"(r7) : "l"(p));
    v[0] = __uint_as_float(r0); v[1] = __uint_as_float(r1);
    v[2] = __uint_as_float(r2); v[3] = __uint_as_float(r3);
    v[4] = __uint_as_float(r4); v[5] = __uint_as_float(r5);
    v[6] = __uint_as_float(r6); v[7] = __uint_as_float(r7);
}

__global__ void __launch_bounds__(NT, 4)
log_entmax_kernel(const float* __restrict__ X, float* __restrict__ Y)
{
    const int tid  = threadIdx.x;
    const int lane = tid & 31;
    const int wid  = tid >> 5;          // 0..11

    __shared__ float4 stage[SH4];       // 48128 B row head
    __shared__ float  sred[4 * NWARP];
    __shared__ float  sbc[3];           // [0]=tau [1]=-log(Z) or sentinel [2]=tau_hi

    const size_t base = (size_t)blockIdx.x * D_DIM;
    const float*  __restrict__ Xs = X + base;
    const float4* __restrict__ Xr = (const float4*)Xs;
    float4*       __restrict__ Yr = (float4*)(Y + base);

    // ---- Pass 1a: staged head — __ldcs + STS, accumulate stats ---------
    float M = -3.0e38f, mn = 3.0e38f, S1 = 0.0f, S2 = 0.0f;
    #pragma unroll
    for (int j = 0; j < NITER_A; j++) {
        const int i4 = tid + j * NT;
        if (i4 < SH4) {
            const float4 v = __ldcs(&Xr[i4]);   // to smem; no L2 reuse
            stage[i4] = v;
            M  = fmaxf(M,  fmaxf(fmaxf(v.x, v.y), fmaxf(v.z, v.w)));
            mn = fminf(mn, fminf(fminf(v.x, v.y), fminf(v.z, v.w)));
            S1 += ((v.x + v.y) + (v.z + v.w));
            S2 = fmaf(v.x, v.x, S2); S2 = fmaf(v.y, v.y, S2);
            S2 = fmaf(v.z, v.z, S2); S2 = fmaf(v.w, v.w, S2);
        }
    }
    // ---- Pass 1b: tail — 256-bit evict_last loads ----------------------
    #pragma unroll
    for (int j = 0; j < NITER_B; j++) {
        const int i8 = SH8 + tid + j * NT;
        if (i8 < NROW8) {
            float v[8];
            ldg256_keep(Xs + i8 * 8, v);
            #pragma unroll
            for (int q = 0; q < 8; q++) {
                M  = fmaxf(M,  v[q]);
                mn = fminf(mn, v[q]);
                S1 += v[q];
                S2 = fmaf(v[q], v[q], S2);
            }
        }
    }

    // ---- Single block reduction of 4 values ----------------------------
    #pragma unroll
    for (int o = 16; o > 0; o >>= 1) {
        M  = fmaxf(M,  __shfl_xor_sync(0xffffffffu, M,  o));
        mn = fminf(mn, __shfl_xor_sync(0xffffffffu, mn, o));
        S1 += __shfl_xor_sync(0xffffffffu, S1, o);
        S2 += __shfl_xor_sync(0xffffffffu, S2, o);
    }
    if (lane == 0) {
        sred[wid] = M; sred[NWARP + wid] = mn;
        sred[2 * NWARP + wid] = S1; sred[3 * NWARP + wid] = S2;
    }
    __syncthreads();
    if (wid == 0) {
        float m = (lane < NWARP) ? sred[lane]             : -3.0e38f;
        float n = (lane < NWARP) ? sred[NWARP + lane]     :  3.0e38f;
        float a = (lane < NWARP) ? sred[2 * NWARP + lane] :  0.0f;
        float b = (lane < NWARP) ? sred[3 * NWARP + lane] :  0.0f;
        #pragma unroll
        for (int o = 8; o > 0; o >>= 1) {
            m = fmaxf(m, __shfl_xor_sync(0xffffffffu, m, o));
            n = fminf(n, __shfl_xor_sync(0xffffffffu, n, o));
            a += __shfl_xor_sync(0xffffffffu, a, o);
            b += __shfl_xor_sync(0xffffffffu, b, o);
        }
        if (lane == 0) {
            // Scalar solve: fp64 accumulation, fp32 sqrt/log
            const double d   = (double)D_DIM;
            const double mu  = 0.5 * (double)a / d;
            const double S2q = 0.25 * (double)b;
            const double V   = S2q - d * mu * mu;        // Sum (Xs - mu)^2
            const double m2  = 0.5 * (double)m;
            const double thi = m2 - TAU_GAP;             // tau_hi
            const double arg = (1.0 - V) / d;
            double t = (arg > 0.0) ? (mu - (double)sqrtf((float)arg)) : (m2 - 1.0);
            if (t > thi)      t = thi;
            if (t < m2 - 1.0) t = m2 - 1.0;
            const float tauf = (float)t;
            const bool dense = (arg > 0.0) && (0.5 * (double)n > (double)tauf);
            const double dmu = mu - (double)tauf;
            const double Z   = V + d * dmu * dmu;        // ~1 by construction
            sbc[0] = tauf;
            sbc[1] = dense ? (-__logf((float)Z)) : 1.0e30f;  // sentinel -> refine
            sbc[2] = (float)thi;
        }
    }
    __syncthreads();
    float tau = sbc[0];
    float nlZ = sbc[1];

    // ---- Fallback: one generic active-set quadratic refinement ---------
    // (plain re-read; never taken on dense-support data)
    if (nlZ > 1.0e29f) {                   // uniform across block
        __syncthreads();
        float C = 0.0f, F1 = 0.0f, F2 = 0.0f;
        #pragma unroll 4
        for (int j = 0; j < 21; j++) {
            const int i4 = tid + j * NT;
            if (i4 < NVROW) {
                const float4 v = Xr[i4];
                #pragma unroll
                for (int q = 0; q < 4; q++) {
                    const float xv = (q == 0) ? v.x : (q == 1) ? v.y : (q == 2) ? v.z : v.w;
                    const float t = fmaf(xv, 0.5f, -tau);
                    const float rr = fmaxf(t, 0.0f);
                    if (t > 0.0f) C += 1.0f;
                    F1 += rr;
                    F2 = fmaf(rr, rr, F2);
                }
            }
        }
        #pragma unroll
        for (int o = 16; o > 0; o >>= 1) {
            C  += __shfl_xor_sync(0xffffffffu, C,  o);
            F1 += __shfl_xor_sync(0xffffffffu, F1, o);
            F2 += __shfl_xor_sync(0xffffffffu, F2, o);
        }
        if (lane == 0) { sred[wid] = C; sred[NWARP + wid] = F1; sred[2 * NWARP + wid] = F2; }
        __syncthreads();
        if (wid == 0) {
            float c  = (lane < NWARP) ? sred[lane]             : 0.0f;
            float f1 = (lane < NWARP) ? sred[NWARP + lane]     : 0.0f;
            float f2 = (lane < NWARP) ? sred[2 * NWARP + lane] : 0.0f;
            #pragma unroll
            for (int o = 8; o > 0; o >>= 1) {
                c  += __shfl_xor_sync(0xffffffffu, c,  o);
                f1 += __shfl_xor_sync(0xffffffffu, f1, o);
                f2 += __shfl_xor_sync(0xffffffffu, f2, o);
            }
            if (lane == 0) {
                float disc = fmaxf(fmaf(-c, f2 - 1.0f, f1 * f1), 0.0f);
                const float delta = (f1 - sqrtf(disc)) / c;
                const float tn = fminf(tau + delta, sbc[2]);
                const float dd = tn - tau;
                const float Zr = fmaf(c, dd * dd, fmaf(-2.0f * f1, dd, f2));
                sbc[0] = tn;
                sbc[1] = -__logf(fmaxf(Zr, 1.0e-30f));
            }
        }
        __syncthreads();
        tau = sbc[0];
        nlZ = sbc[1];
    }

    // ---- Pass 2a: tail re-read FIRST via 256-bit evict_first loads -----
    #pragma unroll 4
    for (int j = 0; j < NITER_C8; j++) {
        const int i8 = SH8 + tid + j * NT;
        if (i8 < NROW8) {
            float v[8];
            ldg256_stream(Xs + i8 * 8, v);
            float4 o0, o1;
            o0.x = fmaf(TWO_LN2, __log2f(fmaxf(fmaf(v[0], 0.5f, -tau), 0.0f)), nlZ);
            o0.y = fmaf(TWO_LN2, __log2f(fmaxf(fmaf(v[1], 0.5f, -tau), 0.0f)), nlZ);
            o0.z = fmaf(TWO_LN2, __log2f(fmaxf(fmaf(v[2], 0.5f, -tau), 0.0f)), nlZ);
            o0.w = fmaf(TWO_LN2, __log2f(fmaxf(fmaf(v[3], 0.5f, -tau), 0.0f)), nlZ);
            o1.x = fmaf(TWO_LN2, __log2f(fmaxf(fmaf(v[4], 0.5f, -tau), 0.0f)), nlZ);
            o1.y = fmaf(TWO_LN2, __log2f(fmaxf(fmaf(v[5], 0.5f, -tau), 0.0f)), nlZ);
            o1.z = fmaf(TWO_LN2, __log2f(fmaxf(fmaf(v[6], 0.5f, -tau), 0.0f)), nlZ);
            o1.w = fmaf(TWO_LN2, __log2f(fmaxf(fmaf(v[7], 0.5f, -tau), 0.0f)), nlZ);
            __stcs(&Yr[2 * i8],     o0);
            __stcs(&Yr[2 * i8 + 1], o1);
        }
    }
    // ---- Pass 2b: staged head from smem, stream output -----------------
    #pragma unroll 4
    for (int j = 0; j < NITER_A; j++) {
        const int i4 = tid + j * NT;
        if (i4 < SH4) {
            const float4 v = stage[i4];
            float4 o;
            o.x = fmaf(TWO_LN2, __log2f(fmaxf(fmaf(v.x, 0.5f, -tau), 0.0f)), nlZ);
            o.y = fmaf(TWO_LN2, __log2f(fmaxf(fmaf(v.y, 0.5f, -tau), 0.0f)), nlZ);
            o.z = fmaf(TWO_LN2, __log2f(fmaxf(fmaf(v.z, 0.5f, -tau), 0.0f)), nlZ);
            o.w = fmaf(TWO_LN2, __log2f(fmaxf(fmaf(v.w, 0.5f, -tau), 0.0f)), nlZ);
            __stcs(&Yr[i4], o);
        }
    }
}

extern "C" void kernel_launch(void* const* d_in, const int* in_sizes, int n_in,
                              void* d_out, int out_size)
{
    const float* X = (const float*)d_in[0];
    float*       Y = (float*)d_out;
    const int rows = in_sizes[0] / D_DIM;     // 4096
    log_entmax_kernel<<<rows, NT>>>(X, Y);
}

// round 15
// speedup vs baseline: 1.2329x; 1.0419x over previous
// LogEntmaxBisect — log(entmax_1.5(X)) for X[4096, 32000] fp32.
//
// R15 = R12 (best, 166.7us) with ONE change: pass-1 sub-loops swapped.
// The pure-load 256-bit evict_last tail loop (highest MLP) now runs FIRST
// at row start — overlapping the previous wave's pass-2 store drain — and
// the mixed __ldcs+STS staging loop runs second. Mirror of R12's winning
// pass-2 swap. R14 lesson: keep 128-bit __ldcs/unroll-4 for the re-read
// (256-bit load + paired stores serialized in L1tex and lost 11us).

#include <cuda_runtime.h>
#include <math.h>

#define D_DIM   32000
#define NT      384
#define NVROW   (D_DIM / 4)       // 8000 float4 per row
#define NROW8   (D_DIM / 8)       // 4000 float8 per row
#define SH4     3008              // staged float4 count (48128 B)
#define SH8     (SH4 / 2)         // 1504 (float8 boundary)
#define NITER_A 8                 // ceil(3008 / 384)     (staged head)
#define NITER_B 7                 // ceil((4000-1504)/384) (256b tail)
#define NITER_C 13                // (8000-3008)/384 exact (L2 re-read)
#define NWARP   (NT / 32)         // 12
#define TAU_GAP 0.005590169943749474   // (1/d)^(alpha-1) = 1/sqrt(32000)
#define TWO_LN2 1.3862943611198906f

// 256-bit load with L2 evict_last (keep for this CTA's pass-2 reuse)
__device__ __forceinline__ void ldg256_keep(const float* p, float* v)
{
    unsigned r0, r1, r2, r3, r4, r5, r6, r7;
    asm("ld.global.L2::evict_last.v8.b32 {%0,%1,%2,%3,%4,%5,%6,%7}, [%8];"
        : "=r"(r0), "=r"(r1), "=r"(r2), "=r"(r3),
          "=r"(r4), "=r"(r5), "=r"(r6), "=r"(r7) : "l"(p));
    v[0] = __uint_as_float(r0); v[1] = __uint_as_float(r1);
    v[2] = __uint_as_float(r2); v[3] = __uint_as_float(r3);
    v[4] = __uint_as_float(r4); v[5] = __uint_as_float(r5);
    v[6] = __uint_as_float(r6); v[7] = __uint_as_float(r7);
}

__global__ void __launch_bounds__(NT, 4)
log_entmax_kernel(const float* __restrict__ X, float* __restrict__ Y)
{
    const int tid  = threadIdx.x;
    const int lane = tid & 31;
    const int wid  = tid >> 5;          // 0..11

    __shared__ float4 stage[SH4];       // 48128 B row head
    __shared__ float  sred[4 * NWARP];
    __shared__ float  sbc[3];           // [0]=tau [1]=-log(Z) or sentinel [2]=tau_hi

    const size_t base = (size_t)blockIdx.x * D_DIM;
    const float*  __restrict__ Xs = X + base;
    const float4* __restrict__ Xr = (const float4*)Xs;
    float4*       __restrict__ Yr = (float4*)(Y + base);

    // ---- Pass 1b FIRST: tail — 256-bit evict_last pure-load loop -------
    float M = -3.0e38f, mn = 3.0e38f, S1 = 0.0f, S2 = 0.0f;
    #pragma unroll
    for (int j = 0; j < NITER_B; j++) {
        const int i8 = SH8 + tid + j * NT;
        if (i8 < NROW8) {
            float v[8];
            ldg256_keep(Xs + i8 * 8, v);
            #pragma unroll
            for (int q = 0; q < 8; q++) {
                M  = fmaxf(M,  v[q]);
                mn = fminf(mn, v[q]);
                S1 += v[q];
                S2 = fmaf(v[q], v[q], S2);
            }
        }
    }
    // ---- Pass 1a: staged head — __ldcs + STS, accumulate stats ---------
    #pragma unroll
    for (int j = 0; j < NITER_A; j++) {
        const int i4 = tid + j * NT;
        if (i4 < SH4) {
            const float4 v = __ldcs(&Xr[i4]);   // to smem; no L2 reuse
            stage[i4] = v;
            M  = fmaxf(M,  fmaxf(fmaxf(v.x, v.y), fmaxf(v.z, v.w)));
            mn = fminf(mn, fminf(fminf(v.x, v.y), fminf(v.z, v.w)));
            S1 += ((v.x + v.y) + (v.z + v.w));
            S2 = fmaf(v.x, v.x, S2); S2 = fmaf(v.y, v.y, S2);
            S2 = fmaf(v.z, v.z, S2); S2 = fmaf(v.w, v.w, S2);
        }
    }

    // ---- Single block reduction of 4 values ----------------------------
    #pragma unroll
    for (int o = 16; o > 0; o >>= 1) {
        M  = fmaxf(M,  __shfl_xor_sync(0xffffffffu, M,  o));
        mn = fminf(mn, __shfl_xor_sync(0xffffffffu, mn, o));
        S1 += __shfl_xor_sync(0xffffffffu, S1, o);
        S2 += __shfl_xor_sync(0xffffffffu, S2, o);
    }
    if (lane == 0) {
        sred[wid] = M; sred[NWARP + wid] = mn;
        sred[2 * NWARP + wid] = S1; sred[3 * NWARP + wid] = S2;
    }
    __syncthreads();
    if (wid == 0) {
        float m = (lane < NWARP) ? sred[lane]             : -3.0e38f;
        float n = (lane < NWARP) ? sred[NWARP + lane]     :  3.0e38f;
        float a = (lane < NWARP) ? sred[2 * NWARP + lane] :  0.0f;
        float b = (lane < NWARP) ? sred[3 * NWARP + lane] :  0.0f;
        #pragma unroll
        for (int o = 8; o > 0; o >>= 1) {
            m = fmaxf(m, __shfl_xor_sync(0xffffffffu, m, o));
            n = fminf(n, __shfl_xor_sync(0xffffffffu, n, o));
            a += __shfl_xor_sync(0xffffffffu, a, o);
            b += __shfl_xor_sync(0xffffffffu, b, o);
        }
        if (lane == 0) {
            // Scalar solve: fp64 accumulation, fp32 sqrt/log
            const double d   = (double)D_DIM;
            const double mu  = 0.5 * (double)a / d;
            const double S2q = 0.25 * (double)b;
            const double V   = S2q - d * mu * mu;        // Sum (Xs - mu)^2
            const double m2  = 0.5 * (double)m;
            const double thi = m2 - TAU_GAP;             // tau_hi
            const double arg = (1.0 - V) / d;
            double t = (arg > 0.0) ? (mu - (double)sqrtf((float)arg)) : (m2 - 1.0);
            if (t > thi)      t = thi;
            if (t < m2 - 1.0) t = m2 - 1.0;
            const float tauf = (float)t;
            const bool dense = (arg > 0.0) && (0.5 * (double)n > (double)tauf);
            const double dmu = mu - (double)tauf;
            const double Z   = V + d * dmu * dmu;        // ~1 by construction
            sbc[0] = tauf;
            sbc[1] = dense ? (-__logf((float)Z)) : 1.0e30f;  // sentinel -> refine
            sbc[2] = (float)thi;
        }
    }
    __syncthreads();
    float tau = sbc[0];
    float nlZ = sbc[1];

    // ---- Fallback: one generic active-set quadratic refinement ---------
    // (plain re-read; never taken on dense-support data)
    if (nlZ > 1.0e29f) {                   // uniform across block
        __syncthreads();
        float C = 0.0f, F1 = 0.0f, F2 = 0.0f;
        #pragma unroll 4
        for (int j = 0; j < 21; j++) {
            const int i4 = tid + j * NT;
            if (i4 < NVROW) {
                const float4 v = Xr[i4];
                #pragma unroll
                for (int q = 0; q < 4; q++) {
                    const float xv = (q == 0) ? v.x : (q == 1) ? v.y : (q == 2) ? v.z : v.w;
                    const float t = fmaf(xv, 0.5f, -tau);
                    const float rr = fmaxf(t, 0.0f);
                    if (t > 0.0f) C += 1.0f;
                    F1 += rr;
                    F2 = fmaf(rr, rr, F2);
                }
            }
        }
        #pragma unroll
        for (int o = 16; o > 0; o >>= 1) {
            C  += __shfl_xor_sync(0xffffffffu, C,  o);
            F1 += __shfl_xor_sync(0xffffffffu, F1, o);
            F2 += __shfl_xor_sync(0xffffffffu, F2, o);
        }
        if (lane == 0) { sred[wid] = C; sred[NWARP + wid] = F1; sred[2 * NWARP + wid] = F2; }
        __syncthreads();
        if (wid == 0) {
            float c  = (lane < NWARP) ? sred[lane]             : 0.0f;
            float f1 = (lane < NWARP) ? sred[NWARP + lane]     : 0.0f;
            float f2 = (lane < NWARP) ? sred[2 * NWARP + lane] : 0.0f;
            #pragma unroll
            for (int o = 8; o > 0; o >>= 1) {
                c  += __shfl_xor_sync(0xffffffffu, c,  o);
                f1 += __shfl_xor_sync(0xffffffffu, f1, o);
                f2 += __shfl_xor_sync(0xffffffffu, f2, o);
            }
            if (lane == 0) {
                float disc = fmaxf(fmaf(-c, f2 - 1.0f, f1 * f1), 0.0f);
                const float delta = (f1 - sqrtf(disc)) / c;
                const float tn = fminf(tau + delta, sbc[2]);
                const float dd = tn - tau;
                const float Zr = fmaf(c, dd * dd, fmaf(-2.0f * f1, dd, f2));
                sbc[0] = tn;
                sbc[1] = -__logf(fmaxf(Zr, 1.0e-30f));
            }
        }
        __syncthreads();
        tau = sbc[0];
        nlZ = sbc[1];
    }

    // ---- Pass 2a: tail re-read (L2-hot, last-use) FIRST ----------------
    #pragma unroll 4
    for (int j = 0; j < NITER_C; j++) {
        const int i4 = SH4 + tid + j * NT;   // exact: 4992 = 13*384
        const float4 v = __ldcs(&Xr[i4]);
        float4 o;
        o.x = fmaf(TWO_LN2, __log2f(fmaxf(fmaf(v.x, 0.5f, -tau), 0.0f)), nlZ);
        o.y = fmaf(TWO_LN2, __log2f(fmaxf(fmaf(v.y, 0.5f, -tau), 0.0f)), nlZ);
        o.z = fmaf(TWO_LN2, __log2f(fmaxf(fmaf(v.z, 0.5f, -tau), 0.0f)), nlZ);
        o.w = fmaf(TWO_LN2, __log2f(fmaxf(fmaf(v.w, 0.5f, -tau), 0.0f)), nlZ);
        __stcs(&Yr[i4], o);
    }
    // ---- Pass 2b: staged head from smem, stream output -----------------
    #pragma unroll 4
    for (int j = 0; j < NITER_A; j++) {
        const int i4 = tid + j * NT;
        if (i4 < SH4) {
            const float4 v = stage[i4];
            float4 o;
            o.x = fmaf(TWO_LN2, __log2f(fmaxf(fmaf(v.x, 0.5f, -tau), 0.0f)), nlZ);
            o.y = fmaf(TWO_LN2, __log2f(fmaxf(fmaf(v.y, 0.5f, -tau), 0.0f)), nlZ);
            o.z = fmaf(TWO_LN2, __log2f(fmaxf(fmaf(v.z, 0.5f, -tau), 0.0f)), nlZ);
            o.w = fmaf(TWO_LN2, __log2f(fmaxf(fmaf(v.w, 0.5f, -tau), 0.0f)), nlZ);
            __stcs(&Yr[i4], o);
        }
    }
}

extern "C" void kernel_launch(void* const* d_in, const int* in_sizes, int n_in,
                              void* d_out, int out_size)
{
    const float* X = (const float*)d_in[0];
    float*       Y = (float*)d_out;
    const int rows = in_sizes[0] / D_DIM;     // 4096
    log_entmax_kernel<<<rows, NT>>>(X, Y);
}

// round 16
// speedup vs baseline: 1.2675x; 1.0281x over previous
// LogEntmaxBisect — log(entmax_1.5(X)) for X[4096, 32000] fp32.
//
// R16 = R12 (best, 166.7us) + solve-bubble prefetch: the first TWO pass-2a
// chunks are loaded (__ldcs, tau-independent addresses) BEFORE the reduce
// barriers and held in registers across the warp-0 solve, so the CTA keeps
// memory traffic in flight through the ~1k-cycle serial section. They are
// emitted first once tau/-logZ arrive. Reg math: M/mn/S1/S2 die at the
// partial store, freeing 4 regs; 2 float4 prefetches need 8 -> net +4
// under the 42-reg launch_bounds cap. All other loop shapes byte-identical
// to R12 (R11/R13/R14/R15 all showed deviations lose).

#include <cuda_runtime.h>
#include <math.h>

#define D_DIM   32000
#define NT      384
#define NVROW   (D_DIM / 4)       // 8000 float4 per row
#define NROW8   (D_DIM / 8)       // 4000 float8 per row
#define SH4     3008              // staged float4 count (48128 B)
#define SH8     (SH4 / 2)         // 1504 (float8 boundary)
#define NITER_A 8                 // ceil(3008 / 384)     (staged head)
#define NITER_B 7                 // ceil((4000-1504)/384) (256b tail)
#define NITER_C 13                // (8000-3008)/384 exact (L2 re-read)
#define NWARP   (NT / 32)         // 12
#define TAU_GAP 0.005590169943749474   // (1/d)^(alpha-1) = 1/sqrt(32000)
#define TWO_LN2 1.3862943611198906f

// 256-bit load with L2 evict_last (keep for this CTA's pass-2 reuse)
__device__ __forceinline__ void ldg256_keep(const float* p, float* v)
{
    unsigned r0, r1, r2, r3, r4, r5, r6, r7;
    asm("ld.global.L2::evict_last.v8.b32 {%0,%1,%2,%3,%4,%5,%6,%7}, [%8];"
        : "=r"(r0), "=r"(r1), "=r"(r2), "=r"(r3),
          "=r"(r4), "=r"(r5), "=r"(r6), "=r"(r7) : "l"(p));
    v[0] = __uint_as_float(r0); v[1] = __uint_as_float(r1);
    v[2] = __uint_as_float(r2); v[3] = __uint_as_float(r3);
    v[4] = __uint_as_float(r4); v[5] = __uint_as_float(r5);
    v[6] = __uint_as_float(r6); v[7] = __uint_as_float(r7);
}

__device__ __forceinline__ void emit4s(float4 v, float tau, float nlZ, float4* dst)
{
    float4 o;
    o.x = fmaf(TWO_LN2, __log2f(fmaxf(fmaf(v.x, 0.5f, -tau), 0.0f)), nlZ);
    o.y = fmaf(TWO_LN2, __log2f(fmaxf(fmaf(v.y, 0.5f, -tau), 0.0f)), nlZ);
    o.z = fmaf(TWO_LN2, __log2f(fmaxf(fmaf(v.z, 0.5f, -tau), 0.0f)), nlZ);
    o.w = fmaf(TWO_LN2, __log2f(fmaxf(fmaf(v.w, 0.5f, -tau), 0.0f)), nlZ);
    __stcs(dst, o);
}

__global__ void __launch_bounds__(NT, 4)
log_entmax_kernel(const float* __restrict__ X, float* __restrict__ Y)
{
    const int tid  = threadIdx.x;
    const int lane = tid & 31;
    const int wid  = tid >> 5;          // 0..11

    __shared__ float4 stage[SH4];       // 48128 B row head
    __shared__ float  sred[4 * NWARP];
    __shared__ float  sbc[3];           // [0]=tau [1]=-log(Z) or sentinel [2]=tau_hi

    const size_t base = (size_t)blockIdx.x * D_DIM;
    const float*  __restrict__ Xs = X + base;
    const float4* __restrict__ Xr = (const float4*)Xs;
    float4*       __restrict__ Yr = (float4*)(Y + base);

    // ---- Pass 1a: staged head — __ldcs + STS, accumulate stats ---------
    float M = -3.0e38f, mn = 3.0e38f, S1 = 0.0f, S2 = 0.0f;
    #pragma unroll
    for (int j = 0; j < NITER_A; j++) {
        const int i4 = tid + j * NT;
        if (i4 < SH4) {
            const float4 v = __ldcs(&Xr[i4]);   // to smem; no L2 reuse
            stage[i4] = v;
            M  = fmaxf(M,  fmaxf(fmaxf(v.x, v.y), fmaxf(v.z, v.w)));
            mn = fminf(mn, fminf(fminf(v.x, v.y), fminf(v.z, v.w)));
            S1 += ((v.x + v.y) + (v.z + v.w));
            S2 = fmaf(v.x, v.x, S2); S2 = fmaf(v.y, v.y, S2);
            S2 = fmaf(v.z, v.z, S2); S2 = fmaf(v.w, v.w, S2);
        }
    }
    // ---- Pass 1b: tail — 256-bit evict_last loads ----------------------
    #pragma unroll
    for (int j = 0; j < NITER_B; j++) {
        const int i8 = SH8 + tid + j * NT;
        if (i8 < NROW8) {
            float v[8];
            ldg256_keep(Xs + i8 * 8, v);
            #pragma unroll
            for (int q = 0; q < 8; q++) {
                M  = fmaxf(M,  v[q]);
                mn = fminf(mn, v[q]);
                S1 += v[q];
                S2 = fmaf(v[q], v[q], S2);
            }
        }
    }

    // ---- Warp reduce, store partials ----------------------------------
    #pragma unroll
    for (int o = 16; o > 0; o >>= 1) {
        M  = fmaxf(M,  __shfl_xor_sync(0xffffffffu, M,  o));
        mn = fminf(mn, __shfl_xor_sync(0xffffffffu, mn, o));
        S1 += __shfl_xor_sync(0xffffffffu, S1, o);
        S2 += __shfl_xor_sync(0xffffffffu, S2, o);
    }
    if (lane == 0) {
        sred[wid] = M; sred[NWARP + wid] = mn;
        sred[2 * NWARP + wid] = S1; sred[3 * NWARP + wid] = S2;
    }

    // ---- Prefetch first two pass-2a chunks across the solve bubble -----
    const float4 pf0 = __ldcs(&Xr[SH4 + tid]);
    const float4 pf1 = __ldcs(&Xr[SH4 + tid + NT]);

    __syncthreads();
    if (wid == 0) {
        float m = (lane < NWARP) ? sred[lane]             : -3.0e38f;
        float n = (lane < NWARP) ? sred[NWARP + lane]     :  3.0e38f;
        float a = (lane < NWARP) ? sred[2 * NWARP + lane] :  0.0f;
        float b = (lane < NWARP) ? sred[3 * NWARP + lane] :  0.0f;
        #pragma unroll
        for (int o = 8; o > 0; o >>= 1) {
            m = fmaxf(m, __shfl_xor_sync(0xffffffffu, m, o));
            n = fminf(n, __shfl_xor_sync(0xffffffffu, n, o));
            a += __shfl_xor_sync(0xffffffffu, a, o);
            b += __shfl_xor_sync(0xffffffffu, b, o);
        }
        if (lane == 0) {
            // Scalar solve: fp64 accumulation, fp32 sqrt/log
            const double d   = (double)D_DIM;
            const double mu  = 0.5 * (double)a / d;
            const double S2q = 0.25 * (double)b;
            const double V   = S2q - d * mu * mu;        // Sum (Xs - mu)^2
            const double m2  = 0.5 * (double)m;
            const double thi = m2 - TAU_GAP;             // tau_hi
            const double arg = (1.0 - V) / d;
            double t = (arg > 0.0) ? (mu - (double)sqrtf((float)arg)) : (m2 - 1.0);
            if (t > thi)      t = thi;
            if (t < m2 - 1.0) t = m2 - 1.0;
            const float tauf = (float)t;
            const bool dense = (arg > 0.0) && (0.5 * (double)n > (double)tauf);
            const double dmu = mu - (double)tauf;
            const double Z   = V + d * dmu * dmu;        // ~1 by construction
            sbc[0] = tauf;
            sbc[1] = dense ? (-__logf((float)Z)) : 1.0e30f;  // sentinel -> refine
            sbc[2] = (float)thi;
        }
    }
    __syncthreads();
    float tau = sbc[0];
    float nlZ = sbc[1];

    // ---- Fallback: one generic active-set quadratic refinement ---------
    // (plain re-read; never taken on dense-support data)
    if (nlZ > 1.0e29f) {                   // uniform across block
        __syncthreads();
        float C = 0.0f, F1 = 0.0f, F2 = 0.0f;
        #pragma unroll 4
        for (int j = 0; j < 21; j++) {
            const int i4 = tid + j * NT;
            if (i4 < NVROW) {
                const float4 v = Xr[i4];
                #pragma unroll
                for (int q = 0; q < 4; q++) {
                    const float xv = (q == 0) ? v.x : (q == 1) ? v.y : (q == 2) ? v.z : v.w;
                    const float t = fmaf(xv, 0.5f, -tau);
                    const float rr = fmaxf(t, 0.0f);
                    if (t > 0.0f) C += 1.0f;
                    F1 += rr;
                    F2 = fmaf(rr, rr, F2);
                }
            }
        }
        #pragma unroll
        for (int o = 16; o > 0; o >>= 1) {
            C  += __shfl_xor_sync(0xffffffffu, C,  o);
            F1 += __shfl_xor_sync(0xffffffffu, F1, o);
            F2 += __shfl_xor_sync(0xffffffffu, F2, o);
        }
        if (lane == 0) { sred[wid] = C; sred[NWARP + wid] = F1; sred[2 * NWARP + wid] = F2; }
        __syncthreads();
        if (wid == 0) {
            float c  = (lane < NWARP) ? sred[lane]             : 0.0f;
            float f1 = (lane < NWARP) ? sred[NWARP + lane]     : 0.0f;
            float f2 = (lane < NWARP) ? sred[2 * NWARP + lane] : 0.0f;
            #pragma unroll
            for (int o = 8; o > 0; o >>= 1) {
                c  += __shfl_xor_sync(0xffffffffu, c,  o);
                f1 += __shfl_xor_sync(0xffffffffu, f1, o);
                f2 += __shfl_xor_sync(0xffffffffu, f2, o);
            }
            if (lane == 0) {
                float disc = fmaxf(fmaf(-c, f2 - 1.0f, f1 * f1), 0.0f);
                const float delta = (f1 - sqrtf(disc)) / c;
                const float tn = fminf(tau + delta, sbc[2]);
                const float dd = tn - tau;
                const float Zr = fmaf(c, dd * dd, fmaf(-2.0f * f1, dd, f2));
                sbc[0] = tn;
                sbc[1] = -__logf(fmaxf(Zr, 1.0e-30f));
            }
        }
        __syncthreads();
        tau = sbc[0];
        nlZ = sbc[1];
    }

    // ---- Pass 2a: emit prefetched chunks, then batched re-read ---------
    emit4s(pf0, tau, nlZ, &Yr[SH4 + tid]);
    emit4s(pf1, tau, nlZ, &Yr[SH4 + tid + NT]);
    #pragma unroll 4
    for (int j = 2; j < NITER_C; j++) {
        const int i4 = SH4 + tid + j * NT;   // exact: 4992 = 13*384
        const float4 v = __ldcs(&Xr[i4]);
        float4 o;
        o.x = fmaf(TWO_LN2, __log2f(fmaxf(fmaf(v.x, 0.5f, -tau), 0.0f)), nlZ);
        o.y = fmaf(TWO_LN2, __log2f(fmaxf(fmaf(v.y, 0.5f, -tau), 0.0f)), nlZ);
        o.z = fmaf(TWO_LN2, __log2f(fmaxf(fmaf(v.z, 0.5f, -tau), 0.0f)), nlZ);
        o.w = fmaf(TWO_LN2, __log2f(fmaxf(fmaf(v.w, 0.5f, -tau), 0.0f)), nlZ);
        __stcs(&Yr[i4], o);
    }
    // ---- Pass 2b: staged head from smem, stream output -----------------
    #pragma unroll 4
    for (int j = 0; j < NITER_A; j++) {
        const int i4 = tid + j * NT;
        if (i4 < SH4) {
            const float4 v = stage[i4];
            float4 o;
            o.x = fmaf(TWO_LN2, __log2f(fmaxf(fmaf(v.x, 0.5f, -tau), 0.0f)), nlZ);
            o.y = fmaf(TWO_LN2, __log2f(fmaxf(fmaf(v.y, 0.5f, -tau), 0.0f)), nlZ);
            o.z = fmaf(TWO_LN2, __log2f(fmaxf(fmaf(v.z, 0.5f, -tau), 0.0f)), nlZ);
            o.w = fmaf(TWO_LN2, __log2f(fmaxf(fmaf(v.w, 0.5f, -tau), 0.0f)), nlZ);
            __stcs(&Yr[i4], o);
        }
    }
}

extern "C" void kernel_launch(void* const* d_in, const int* in_sizes, int n_in,
                              void* d_out, int out_size)
{
    const float* X = (const float*)d_in[0];
    float*       Y = (float*)d_out;
    const int rows = in_sizes[0] / D_DIM;     // 4096
    log_entmax_kernel<<<rows, NT>>>(X, Y);
}